// round 4
// baseline (speedup 1.0000x reference)
#include <cuda_runtime.h>

// Problem constants (fixed by the dataset)
#define NMAX 50000
#define EMAX 1000000
#define DIN  64
#define H1   64
#define H2   64
#define RNUM 8
#define BNUM 30
#define JTOT 576   // RNUM*H1 (relation cols) + H1 (self-loop cols)

// ---------------- static device scratch (no allocs allowed) ----------------
__device__ float g_Wcat[DIN * JTOT];                 // [k][j] fused relation+loop weights
__device__ float g_xr[(size_t)NMAX * JTOT];          // x @ Wcat  (115 MB, ~L2 resident)
__device__ float g_hs[(size_t)NMAX * H1];            // layer-1 output, pre-scaled by rsqrt(deg_out)
__device__ int   g_deg_out[NMAX];
__device__ int   g_deg_in[NMAX];
__device__ int   g_cursor[NMAX];
__device__ int   g_rowoff[NMAX + 1];
__device__ int   g_csr[EMAX];                        // packed: src | (etype << 17)

// ---------------- K0: zero counters ----------------
__global__ void zero_kernel(int n) {
    int i = blockIdx.x * blockDim.x + threadIdx.x;
    if (i < n) { g_deg_in[i] = 0; g_deg_out[i] = 0; g_cursor[i] = 0; }
}

// ---------------- K1: Wcat = [comp@basis (r-major cols) | loop_weight] ----------------
__global__ void wcat_kernel(const float* __restrict__ basis,
                            const float* __restrict__ comp,
                            const float* __restrict__ loopw) {
    int idx = blockIdx.x * blockDim.x + threadIdx.x;
    if (idx < RNUM * DIN * H1) {
        int o = idx & 63;
        int i = (idx >> 6) & 63;
        int r = idx >> 12;
        float s = 0.f;
#pragma unroll
        for (int b = 0; b < BNUM; b++)
            s += comp[r * BNUM + b] * basis[(b * DIN + i) * H1 + o];
        g_Wcat[i * JTOT + r * 64 + o] = s;
    } else if (idx < RNUM * DIN * H1 + DIN * H1) {
        int j = idx - RNUM * DIN * H1;
        int o = j & 63;
        int i = j >> 6;
        g_Wcat[i * JTOT + RNUM * 64 + o] = loopw[i * H1 + o];
    }
}

// ---------------- K2: degree counts (edge_index is int32: JAX x64 disabled) ----------------
__global__ void deg_kernel(const int* __restrict__ ei, int e) {
    int i = blockIdx.x * blockDim.x + threadIdx.x;
    if (i < e) {
        int s = ei[i];
        int d = ei[e + i];
        atomicAdd(&g_deg_out[s], 1);
        atomicAdd(&g_deg_in[d], 1);
    }
}

// ---------------- K3: single-block exclusive scan of deg_in -> rowoff ----------------
__global__ void scan_kernel(int n) {
    __shared__ int shWS[32];
    __shared__ int s_carry;
    int tid = threadIdx.x, lane = tid & 31, wid = tid >> 5;
    if (tid == 0) { s_carry = 0; g_rowoff[0] = 0; }
    __syncthreads();
    for (int base = 0; base < n; base += 1024) {
        int i = base + tid;
        int v = (i < n) ? g_deg_in[i] : 0;
        int sc = v;
#pragma unroll
        for (int off = 1; off < 32; off <<= 1) {
            int t = __shfl_up_sync(0xFFFFFFFFu, sc, off);
            if (lane >= off) sc += t;
        }
        if (lane == 31) shWS[wid] = sc;
        __syncthreads();
        if (wid == 0) {
            int ws = shWS[lane];
            int s2 = ws;
#pragma unroll
            for (int off = 1; off < 32; off <<= 1) {
                int t = __shfl_up_sync(0xFFFFFFFFu, s2, off);
                if (lane >= off) s2 += t;
            }
            shWS[lane] = s2 - ws;  // exclusive warp offsets
        }
        __syncthreads();
        int incl = sc + shWS[wid] + s_carry;
        if (i < n) g_rowoff[i + 1] = incl;
        __syncthreads();              // everyone read s_carry before update
        if (tid == 1023) s_carry = incl;
        __syncthreads();
    }
}

// ---------------- K4: fill CSR (dst -> packed (src, etype)) ----------------
__global__ void fill_kernel(const int* __restrict__ ei,
                            const int* __restrict__ et, int e) {
    int i = blockIdx.x * blockDim.x + threadIdx.x;
    if (i < e) {
        int s = ei[i];
        int d = ei[e + i];
        int r = et[i];
        int pos = g_rowoff[d] + atomicAdd(&g_cursor[d], 1);
        g_csr[pos] = s | (r << 17);   // src < 2^17, r < 8
    }
}

// ---------------- K5: xr = x @ Wcat  (tiled GEMM, 64x64 tile, 4x4 reg blocking) ----------------
__global__ void gemm_xr_kernel(const float* __restrict__ x, int n) {
    __shared__ float shW[64][64];   // [k][col]
    __shared__ float shX[64][65];   // [node][k], padded
    int jt  = blockIdx.x * 64;
    int nt  = blockIdx.y * 64;
    int tid = threadIdx.x;          // 256

    for (int i = tid; i < 64 * 64; i += 256) {
        int k = i >> 6, c = i & 63;
        shW[k][c] = g_Wcat[k * JTOT + jt + c];
    }
    for (int i = tid; i < 64 * 64; i += 256) {
        int r = i >> 6, k = i & 63;
        int node = nt + r;
        shX[r][k] = (node < n) ? x[node * DIN + k] : 0.f;
    }
    __syncthreads();

    int tx = tid & 15;   // 4 cols
    int ty = tid >> 4;   // 4 nodes
    float acc[4][4] = {};
#pragma unroll
    for (int k = 0; k < 64; k++) {
        float b0 = shW[k][tx * 4 + 0];
        float b1 = shW[k][tx * 4 + 1];
        float b2 = shW[k][tx * 4 + 2];
        float b3 = shW[k][tx * 4 + 3];
#pragma unroll
        for (int i = 0; i < 4; i++) {
            float a = shX[ty * 4 + i][k];
            acc[i][0] += a * b0;
            acc[i][1] += a * b1;
            acc[i][2] += a * b2;
            acc[i][3] += a * b3;
        }
    }
#pragma unroll
    for (int i = 0; i < 4; i++) {
        int node = nt + ty * 4 + i;
        if (node < n) {
            float4 v = make_float4(acc[i][0], acc[i][1], acc[i][2], acc[i][3]);
            *(float4*)&g_xr[(size_t)node * JTOT + jt + tx * 4] = v;
        }
    }
}

// ---------------- K6: layer-1 aggregate + self loop + bias, store hs ----------------
__global__ void agg1_kernel(const float* __restrict__ bias1, int n) {
    int gw   = (blockIdx.x * blockDim.x + threadIdx.x) >> 5;
    int lane = threadIdx.x & 31;
    if (gw >= n) return;
    int beg = g_rowoff[gw], end = g_rowoff[gw + 1];

    const float* xl = &g_xr[(size_t)gw * JTOT + RNUM * 64];  // self-loop cols
    float a0 = bias1[lane]      + xl[lane];
    float a1 = bias1[lane + 32] + xl[lane + 32];

    int e = beg;
    for (; e + 1 < end; e += 2) {
        int p0 = g_csr[e], p1 = g_csr[e + 1];
        const float* m0 = &g_xr[(size_t)(p0 & 0x1FFFF) * JTOT + ((p0 >> 17) << 6)];
        const float* m1 = &g_xr[(size_t)(p1 & 0x1FFFF) * JTOT + ((p1 >> 17) << 6)];
        float v00 = m0[lane],      v10 = m1[lane];
        float v01 = m0[lane + 32], v11 = m1[lane + 32];
        a0 += v00 + v10;
        a1 += v01 + v11;
    }
    if (e < end) {
        int p0 = g_csr[e];
        const float* m0 = &g_xr[(size_t)(p0 & 0x1FFFF) * JTOT + ((p0 >> 17) << 6)];
        a0 += m0[lane];
        a1 += m0[lane + 32];
    }
    float sc = rsqrtf((float)max(g_deg_out[gw], 1));
    g_hs[(size_t)gw * H1 + lane]      = a0 * sc;
    g_hs[(size_t)gw * H1 + lane + 32] = a1 * sc;
}

// ---------------- K7: layer-2 aggregate + rsqrt(deg_in) + @W2 + bias2 ----------------
__global__ void agg2_kernel(const float* __restrict__ w2,
                            const float* __restrict__ bias2,
                            float* __restrict__ out, int n) {
    __shared__ float shW[H1 * H2];   // 16 KB
    __shared__ float shT[8][H1];
    int tid = threadIdx.x;
    for (int i = tid; i < H1 * H2; i += 256) shW[i] = w2[i];
    __syncthreads();

    int w = tid >> 5, lane = tid & 31;
    int d = blockIdx.x * 8 + w;
    if (d >= n) return;
    int beg = g_rowoff[d], end = g_rowoff[d + 1];

    float a0 = 0.f, a1 = 0.f;
    int e = beg;
    for (; e + 1 < end; e += 2) {
        int p0 = g_csr[e] & 0x1FFFF, p1 = g_csr[e + 1] & 0x1FFFF;
        const float* h0 = &g_hs[(size_t)p0 * H1];
        const float* h1 = &g_hs[(size_t)p1 * H1];
        float v00 = h0[lane],      v10 = h1[lane];
        float v01 = h0[lane + 32], v11 = h1[lane + 32];
        a0 += v00 + v10;
        a1 += v01 + v11;
    }
    if (e < end) {
        int p = g_csr[e] & 0x1FFFF;
        a0 += g_hs[(size_t)p * H1 + lane];
        a1 += g_hs[(size_t)p * H1 + lane + 32];
    }
    float sc = rsqrtf((float)max(end - beg, 1));
    shT[w][lane]      = a0 * sc;
    shT[w][lane + 32] = a1 * sc;
    __syncwarp();

    float o0 = bias2[lane], o1 = bias2[lane + 32];
#pragma unroll 8
    for (int i = 0; i < 64; i++) {
        float t = shT[w][i];
        o0 += t * shW[i * H2 + lane];
        o1 += t * shW[i * H2 + lane + 32];
    }
    out[(size_t)d * H2 + lane]      = o0;
    out[(size_t)d * H2 + lane + 32] = o1;
}

// ---------------- launch ----------------
extern "C" void kernel_launch(void* const* d_in, const int* in_sizes, int n_in,
                              void* d_out, int out_size) {
    const float* x     = (const float*)d_in[0];
    const int*   ei    = (const int*)d_in[1];   // int32: JAX default x64-disabled
    // d_in[2] = edge_norm : UNUSED by the reference
    const int*   et    = (const int*)d_in[3];   // int32
    const float* basis = (const float*)d_in[4];
    const float* comp  = (const float*)d_in[5];
    const float* loopw = (const float*)d_in[6];
    const float* bias1 = (const float*)d_in[7];
    const float* w2    = (const float*)d_in[8];
    const float* bias2 = (const float*)d_in[9];
    float* out = (float*)d_out;

    int n = in_sizes[0] / DIN;   // 50000
    int e = in_sizes[1] / 2;     // 1000000

    zero_kernel<<<(n + 255) / 256, 256>>>(n);
    wcat_kernel<<<(RNUM * DIN * H1 + DIN * H1 + 255) / 256, 256>>>(basis, comp, loopw);
    deg_kernel<<<(e + 255) / 256, 256>>>(ei, e);
    scan_kernel<<<1, 1024>>>(n);
    fill_kernel<<<(e + 255) / 256, 256>>>(ei, et, e);

    dim3 g4(JTOT / 64, (n + 63) / 64);
    gemm_xr_kernel<<<g4, 256>>>(x, n);

    agg1_kernel<<<((n * 32) + 255) / 256, 256>>>(bias1, n);
    agg2_kernel<<<(n + 7) / 8, 256>>>(w2, bias2, out, n);
}

// round 5
// speedup vs baseline: 1.2401x; 1.2401x over previous
#include <cuda_runtime.h>

// Problem constants
#define NMAX 50000
#define EMAX 1000000
#define DIN  64
#define RNUM 8
#define BNUM 30
#define JTOT 576          // 8*64 relation cols + 64 self-loop cols
#define SCANPAD 65536     // 4 scan iterations * 16384

// ---------------- static device scratch ----------------
__device__ float g_Wcat[JTOT * 64];              // [kk][o], kk = r*64+i or 512+i
__device__ float g_z[(size_t)NMAX * JTOT];       // per-dst relation sums | self x
__device__ float g_hs[(size_t)NMAX * 64];        // layer-1 out, scaled by rsqrt(deg_out)
__device__ float g_g[(size_t)NMAX * 64];         // hs @ W2
__device__ int   g_deg_out[NMAX];
__device__ int   g_deg_in[SCANPAD];              // padded+zeroed for int4 scan
__device__ int   g_cursor[NMAX];
__device__ int   g_rowoff[NMAX + 1];
__device__ int   g_csr[EMAX];                    // src | (etype << 17)

// ---------------- f32x2 packed-FMA helpers ----------------
typedef unsigned long long ull;
__device__ __forceinline__ ull pack2(float lo, float hi) {
    ull r; asm("mov.b64 %0,{%1,%2};" : "=l"(r) : "f"(lo), "f"(hi)); return r;
}
__device__ __forceinline__ void unpack2(ull v, float& lo, float& hi) {
    asm("mov.b64 {%0,%1},%2;" : "=f"(lo), "=f"(hi) : "l"(v));
}
__device__ __forceinline__ void ffma2(ull& d, ull a, ull b) {
    asm("fma.rn.f32x2 %0,%1,%2,%0;" : "+l"(d) : "l"(a), "l"(b));
}

// ---------------- K0: zero counters (deg_in padded for int4 scan) ----------------
__global__ void zero_kernel(int n) {
    int i = blockIdx.x * blockDim.x + threadIdx.x;
    if (i < SCANPAD) g_deg_in[i] = 0;
    if (i < n) { g_deg_out[i] = 0; g_cursor[i] = 0; }
}

// ---------------- K1: Wcat[kk][o] = Wrel / loop weights ----------------
__global__ void wcat_kernel(const float* __restrict__ basis,
                            const float* __restrict__ comp,
                            const float* __restrict__ loopw) {
    int idx = blockIdx.x * blockDim.x + threadIdx.x;
    if (idx >= JTOT * 64) return;
    int o = idx & 63;
    int kk = idx >> 6;
    if (kk < RNUM * 64) {
        int r = kk >> 6, i = kk & 63;
        float s = 0.f;
#pragma unroll
        for (int b = 0; b < BNUM; b++)
            s += comp[r * BNUM + b] * basis[(b * DIN + i) * 64 + o];
        g_Wcat[kk * 64 + o] = s;
    } else {
        int i = kk - RNUM * 64;
        g_Wcat[kk * 64 + o] = loopw[i * 64 + o];
    }
}

// ---------------- K2: degree counts ----------------
__global__ void deg_kernel(const int* __restrict__ ei, int e) {
    int i = blockIdx.x * blockDim.x + threadIdx.x;
    if (i < e) {
        atomicAdd(&g_deg_out[ei[i]], 1);
        atomicAdd(&g_deg_in[ei[e + i]], 1);
    }
}

// ---------------- K3: single-block scan, 16 elems/thread (int4) ----------------
__global__ void scan_kernel(int n) {
    __shared__ int wsum[32];
    __shared__ int s_carry, s_total;
    int tid = threadIdx.x, lane = tid & 31, wid = tid >> 5;
    if (tid == 0) { s_carry = 0; g_rowoff[0] = 0; }
    __syncthreads();
    for (int base = 0; base < n; base += 1024 * 16) {
        int idx0 = base + tid * 16;
        int v[16];
#pragma unroll
        for (int q = 0; q < 4; q++) {
            int4 t = *(const int4*)&g_deg_in[idx0 + q * 4];
            v[q * 4] = t.x; v[q * 4 + 1] = t.y; v[q * 4 + 2] = t.z; v[q * 4 + 3] = t.w;
        }
        int tsum = 0;
#pragma unroll
        for (int j = 0; j < 16; j++) tsum += v[j];
        int sc = tsum;
#pragma unroll
        for (int off = 1; off < 32; off <<= 1) {
            int t = __shfl_up_sync(0xFFFFFFFFu, sc, off);
            if (lane >= off) sc += t;
        }
        if (lane == 31) wsum[wid] = sc;
        __syncthreads();
        if (wid == 0) {
            int w = wsum[lane];
            int s2 = w;
#pragma unroll
            for (int off = 1; off < 32; off <<= 1) {
                int t = __shfl_up_sync(0xFFFFFFFFu, s2, off);
                if (lane >= off) s2 += t;
            }
            wsum[lane] = s2 - w;
            if (lane == 31) s_total = s2;
        }
        __syncthreads();
        int run = sc - tsum + wsum[wid] + s_carry;   // exclusive prefix for this thread
#pragma unroll
        for (int j = 0; j < 16; j++) {
            run += v[j];
            int i = idx0 + j;
            if (i < n) g_rowoff[i + 1] = run;
        }
        __syncthreads();
        if (tid == 0) s_carry += s_total;
        __syncthreads();
    }
}

// ---------------- K4: fill CSR ----------------
__global__ void fill_kernel(const int* __restrict__ ei,
                            const int* __restrict__ et, int e) {
    int i = blockIdx.x * blockDim.x + threadIdx.x;
    if (i < e) {
        int d = ei[e + i];
        int pos = g_rowoff[d] + atomicAdd(&g_cursor[d], 1);
        g_csr[pos] = ei[i] | (et[i] << 17);
    }
}

// ---------------- K5: aggregate raw x per (dst, relation) -> z ----------------
__global__ void aggz_kernel(const float* __restrict__ x, int n) {
    int gw   = (blockIdx.x * blockDim.x + threadIdx.x) >> 5;
    int lane = threadIdx.x & 31;
    if (gw >= n) return;
    int beg = g_rowoff[gw], end = g_rowoff[gw + 1];

    float a0[RNUM] = {}, a1[RNUM] = {};
    int e = beg;
    for (; e + 1 < end; e += 2) {
        int p0 = g_csr[e], p1 = g_csr[e + 1];
        const float* s0 = &x[(size_t)(p0 & 0x1FFFF) * 64];
        const float* s1 = &x[(size_t)(p1 & 0x1FFFF) * 64];
        int r0 = p0 >> 17, r1 = p1 >> 17;
        float v00 = s0[lane], v01 = s0[lane + 32];
        float v10 = s1[lane], v11 = s1[lane + 32];
#pragma unroll
        for (int r = 0; r < RNUM; r++) {
            a0[r] += (r == r0) ? v00 : 0.f;
            a1[r] += (r == r0) ? v01 : 0.f;
            a0[r] += (r == r1) ? v10 : 0.f;
            a1[r] += (r == r1) ? v11 : 0.f;
        }
    }
    if (e < end) {
        int p0 = g_csr[e];
        const float* s0 = &x[(size_t)(p0 & 0x1FFFF) * 64];
        int r0 = p0 >> 17;
        float v00 = s0[lane], v01 = s0[lane + 32];
#pragma unroll
        for (int r = 0; r < RNUM; r++) {
            a0[r] += (r == r0) ? v00 : 0.f;
            a1[r] += (r == r0) ? v01 : 0.f;
        }
    }
    float* zr = &g_z[(size_t)gw * JTOT];
#pragma unroll
    for (int r = 0; r < RNUM; r++) {
        __stcs(&zr[r * 64 + lane],      a0[r]);
        __stcs(&zr[r * 64 + lane + 32], a1[r]);
    }
    __stcs(&zr[512 + lane],      x[(size_t)gw * 64 + lane]);
    __stcs(&zr[512 + lane + 32], x[(size_t)gw * 64 + lane + 32]);
}

// ---------------- K6: generic 128x64 GEMM with f32x2 FMA ----------------
// asel=0: A=g_z (K=576), C=g_hs, B=g_Wcat, mode=1 (bias1 + rsqrt(deg_out) scale)
// asel=1: A=g_hs (K=64),  C=g_g,  B=w2,     mode=0
__global__ __launch_bounds__(256) void gemm_kernel(int asel, const float* __restrict__ Bopt,
                                                   const float* __restrict__ bias,
                                                   int M, int K, int mode) {
    __shared__ float shA[32][132];   // [k][m], padded
    __shared__ float shB[32][64];
    const float* A = asel ? g_hs : g_z;
    float*       C = asel ? g_g  : g_hs;
    const float* B = Bopt ? Bopt : g_Wcat;

    int tid = threadIdx.x;
    int tx = tid & 15, ty = tid >> 4;        // tx: 4-col group, ty: 8-row group
    int mBase = blockIdx.x * 128;
    int rowL = tid >> 1, half = tid & 1;
    int gr = mBase + rowL;

    ull acc[4][4] = {};
    for (int k0 = 0; k0 < K; k0 += 32) {
        __syncthreads();
        // stage A (transpose to [k][m])
#pragma unroll
        for (int q = 0; q < 4; q++) {
            int kk = half * 16 + q * 4;
            float4 v = make_float4(0.f, 0.f, 0.f, 0.f);
            if (gr < M) v = __ldcs((const float4*)&A[(size_t)gr * K + k0 + kk]);
            shA[kk][rowL] = v.x; shA[kk + 1][rowL] = v.y;
            shA[kk + 2][rowL] = v.z; shA[kk + 3][rowL] = v.w;
        }
        // stage B
        {
            int f = tid * 8, kr = f >> 6, c = f & 63;
            *(float4*)&shB[kr][c]     = *(const float4*)&B[(size_t)(k0 + kr) * 64 + c];
            *(float4*)&shB[kr][c + 4] = *(const float4*)&B[(size_t)(k0 + kr) * 64 + c + 4];
        }
        __syncthreads();
#pragma unroll
        for (int k = 0; k < 32; k++) {
            float4 b = *(const float4*)&shB[k][tx * 4];
            ull bd0 = pack2(b.x, b.x), bd1 = pack2(b.y, b.y);
            ull bd2 = pack2(b.z, b.z), bd3 = pack2(b.w, b.w);
#pragma unroll
            for (int i = 0; i < 4; i++) {
                ull a = *(const ull*)&shA[k][ty * 8 + 2 * i];
                ffma2(acc[i][0], a, bd0);
                ffma2(acc[i][1], a, bd1);
                ffma2(acc[i][2], a, bd2);
                ffma2(acc[i][3], a, bd3);
            }
        }
    }
    // epilogue
#pragma unroll
    for (int i = 0; i < 4; i++) {
        float lo[4], hi[4];
#pragma unroll
        for (int j = 0; j < 4; j++) unpack2(acc[i][j], lo[j], hi[j]);
        int g0 = mBase + ty * 8 + 2 * i, g1 = g0 + 1;
        if (g0 < M) {
            float4 o;
            if (mode) {
                float s = rsqrtf((float)max(g_deg_out[g0], 1));
                o = make_float4((lo[0] + bias[tx * 4]) * s, (lo[1] + bias[tx * 4 + 1]) * s,
                                (lo[2] + bias[tx * 4 + 2]) * s, (lo[3] + bias[tx * 4 + 3]) * s);
            } else o = make_float4(lo[0], lo[1], lo[2], lo[3]);
            *(float4*)&C[(size_t)g0 * 64 + tx * 4] = o;
        }
        if (g1 < M) {
            float4 o;
            if (mode) {
                float s = rsqrtf((float)max(g_deg_out[g1], 1));
                o = make_float4((hi[0] + bias[tx * 4]) * s, (hi[1] + bias[tx * 4 + 1]) * s,
                                (hi[2] + bias[tx * 4 + 2]) * s, (hi[3] + bias[tx * 4 + 3]) * s);
            } else o = make_float4(hi[0], hi[1], hi[2], hi[3]);
            *(float4*)&C[(size_t)g1 * 64 + tx * 4] = o;
        }
    }
}

// ---------------- K7: final aggregation: out = rsqrt(deg_in)*sum g[src] + bias2 ----------------
__global__ void agg3_kernel(const float* __restrict__ bias2,
                            float* __restrict__ out, int n) {
    int gw   = (blockIdx.x * blockDim.x + threadIdx.x) >> 5;
    int lane = threadIdx.x & 31;
    if (gw >= n) return;
    int beg = g_rowoff[gw], end = g_rowoff[gw + 1];

    float a0 = 0.f, a1 = 0.f;
    int e = beg;
    for (; e + 1 < end; e += 2) {
        int p0 = g_csr[e] & 0x1FFFF, p1 = g_csr[e + 1] & 0x1FFFF;
        const float* h0 = &g_g[(size_t)p0 * 64];
        const float* h1 = &g_g[(size_t)p1 * 64];
        a0 += h0[lane]      + h1[lane];
        a1 += h0[lane + 32] + h1[lane + 32];
    }
    if (e < end) {
        int p = g_csr[e] & 0x1FFFF;
        a0 += g_g[(size_t)p * 64 + lane];
        a1 += g_g[(size_t)p * 64 + lane + 32];
    }
    float sc = rsqrtf((float)max(end - beg, 1));
    out[(size_t)gw * 64 + lane]      = a0 * sc + bias2[lane];
    out[(size_t)gw * 64 + lane + 32] = a1 * sc + bias2[lane + 32];
}

// ---------------- launch ----------------
extern "C" void kernel_launch(void* const* d_in, const int* in_sizes, int n_in,
                              void* d_out, int out_size) {
    const float* x     = (const float*)d_in[0];
    const int*   ei    = (const int*)d_in[1];   // int32 (JAX x64 disabled)
    const int*   et    = (const int*)d_in[3];   // int32
    const float* basis = (const float*)d_in[4];
    const float* comp  = (const float*)d_in[5];
    const float* loopw = (const float*)d_in[6];
    const float* bias1 = (const float*)d_in[7];
    const float* w2    = (const float*)d_in[8];
    const float* bias2 = (const float*)d_in[9];
    float* out = (float*)d_out;

    int n = in_sizes[0] / DIN;   // 50000
    int e = in_sizes[1] / 2;     // 1000000

    zero_kernel<<<(SCANPAD + 255) / 256, 256>>>(n);
    wcat_kernel<<<(JTOT * 64 + 255) / 256, 256>>>(basis, comp, loopw);
    deg_kernel<<<(e + 255) / 256, 256>>>(ei, e);
    scan_kernel<<<1, 1024>>>(n);
    fill_kernel<<<(e + 255) / 256, 256>>>(ei, et, e);

    aggz_kernel<<<(n * 32 + 255) / 256, 256>>>(x, n);

    int mb = (n + 127) / 128;
    gemm_kernel<<<mb, 256>>>(0, nullptr, bias1, n, JTOT, 1);   // hs = (z@Wcat + b1)*rsqrt(deg_out)
    gemm_kernel<<<mb, 256>>>(1, w2, nullptr, n, 64, 0);        // g  = hs @ W2

    agg3_kernel<<<(n * 32 + 255) / 256, 256>>>(bias2, out, n);
}